// round 15
// baseline (speedup 1.0000x reference)
#include <cuda_runtime.h>
#include <cuda_fp16.h>

#define Bz 2
#define Vn 4
#define Cn 32
#define Hf 64
#define Wf 64
#define Dv 64
#define QV 65536            // uint4 (16B) units per view: 4096 texels x 16 chpairs

// Q layout: [bv][tex][chpair(16)][tap(4)][ch(2)] fp16; texel record = 256B
__device__ uint4 g_Q[Bz*Vn*QV];              // 8 MB
__device__ float g_cam[Bz*Vn][16];

// ---------------------------------------------------------------------------
// Pack: f [bv][c][y][x] fp32 -> g_Q. Block = (bv, y-row), 512 threads.
// ---------------------------------------------------------------------------
__global__ __launch_bounds__(512) void pack_kernel(
        const float* __restrict__ f,
        const float* __restrict__ R, const float* __restrict__ T,
        const float* __restrict__ K, const float* __restrict__ root) {
    __shared__ __half s_f[2][32][66];        // [row][c][x + pad2]
    const int tid = threadIdx.x;
    const int bv  = blockIdx.x >> 6;
    const int y0  = blockIdx.x & 63;

    #pragma unroll
    for (int it = 0; it < 2; it++) {
        const int k   = tid + it*512;
        const int x4  = (k & 15) * 4;
        const int c   = (k >> 4) & 31;
        const int row = k >> 9;
        const int gy  = min(y0 + row, 63);
        const float4 a = __ldg(reinterpret_cast<const float4*>(
            &f[(((bv*Cn + c)*Hf) + gy)*Wf + x4]));
        const __half2 h0 = __floats2half2_rn(a.x, a.y);
        const __half2 h1 = __floats2half2_rn(a.z, a.w);
        *reinterpret_cast<__half2*>(&s_f[row][c][x4    ]) = h0;
        *reinterpret_cast<__half2*>(&s_f[row][c][x4 + 2]) = h1;
    }

    if (blockIdx.x == 0 && tid < Bz*Vn) {
        int i = tid, b = i / Vn;
        const float* Ri = R + i*9; const float* Ti = T + i*3;
        const float* Ki = K + i*9; const float* rb = root + b*3;
        float* o = g_cam[i];
        #pragma unroll
        for (int r = 0; r < 9; r++) o[r] = Ri[r];
        #pragma unroll
        for (int r = 0; r < 3; r++)
            o[9+r] = Ri[r*3+0]*rb[0] + Ri[r*3+1]*rb[1] + Ri[r*3+2]*rb[2] + Ti[r];
        o[12] = Ki[0]; o[13] = Ki[4]; o[14] = Ki[2]; o[15] = Ki[5];
    }
    __syncthreads();

    #pragma unroll
    for (int it = 0; it < 2; it++) {
        const int k = tid + it*512;
        const int q = k & 15;
        const int x = (k >> 4) & 63;
        const int e  = x & ~1;
        const int i0 = x - e;
        const int i1 = min(x + 1, 63) - e;

        uint4 u;
        #pragma unroll
        for (int r = 0; r < 2; r++) {
            const unsigned* rowA = reinterpret_cast<const unsigned*>(&s_f[r][2*q    ][0]);
            const unsigned* rowB = reinterpret_cast<const unsigned*>(&s_f[r][2*q + 1][0]);
            const unsigned A0 = rowA[(e >> 1)    ];
            const unsigned A1 = rowA[(e >> 1) + 1];
            const unsigned B0 = rowB[(e >> 1)    ];
            const unsigned B1 = rowB[(e >> 1) + 1];
            const unsigned vx = __byte_perm(A0, B0, i0 ? 0x7632 : 0x5410);
            const unsigned vy = (i1 == 2) ? __byte_perm(A1, B1, 0x5410)
                                          : __byte_perm(A0, B0, 0x7632);
            if (r == 0) { u.x = vx; u.y = vy; } else { u.z = vx; u.w = vy; }
        }
        g_Q[bv*QV + (y0*64 + x)*16 + q] = u;
    }
}

#define FMA4(acc, ww, d)                                                              \
    acc = __hfma2(*reinterpret_cast<const __half2*>(&(ww).x),                         \
                  *reinterpret_cast<const __half2*>(&(d).x), acc);                    \
    acc = __hfma2(*reinterpret_cast<const __half2*>(&(ww).y),                         \
                  *reinterpret_cast<const __half2*>(&(d).y), acc);                    \
    acc = __hfma2(*reinterpret_cast<const __half2*>(&(ww).z),                         \
                  *reinterpret_cast<const __half2*>(&(d).z), acc);                    \
    acc = __hfma2(*reinterpret_cast<const __half2*>(&(ww).w),                         \
                  *reinterpret_cast<const __half2*>(&(d).w), acc);

// ---------------------------------------------------------------------------
// Main kernel. Tile 32x4x1, 512 threads, 3 blocks/SM.
// Phase 2: all 8 LDG.128 of an iteration issued back-to-back (MLP=8);
//          scalar STS.32 into pad-33 rows (8B-alignment NOT guaranteed).
// ---------------------------------------------------------------------------
__global__ __launch_bounds__(512, 3) void sample_kernel(float* __restrict__ out) {
    __shared__ float s_cam[128];
    __shared__ uint4 s_ww[128][Vn];
    __shared__ int4  s_off4[128];
    __shared__ float s_acc[128][Cn + 1];

    const int tid = threadIdx.x;
    const int bid = blockIdx.x;
    const int b   = bid >> 11;
    const int t   = bid & 2047;
    const int x0t = (t & 1) * 32;
    const int y0t = ((t >> 1) & 15) * 4;
    const int z0t = t >> 5;

    if (tid < 128) s_cam[tid] = reinterpret_cast<const float*>(g_cam)[b*64 + tid];
    __syncthreads();

    // -------- Phase 1: projection + weight remap --------
    {
        const int pl = tid >> 2;
        const int v  = tid & 3;
        const int xi = x0t + (pl & 31);
        const int yi = y0t + (pl >> 5);
        const int zi = z0t;

        const float wx = (xi * (1.0f/63.0f) - 0.5f) * 0.2f;
        const float wy = (yi * (1.0f/63.0f) - 0.5f) * 0.2f;
        const float wz = (zi * (1.0f/63.0f) - 0.5f) * 0.2f;

        const float* cam = &s_cam[v*16];
        const float Xc = cam[0]*wx + cam[1]*wy + cam[2]*wz + cam[9];
        const float Yc = cam[3]*wx + cam[4]*wy + cam[5]*wz + cam[10];
        const float Zc = cam[6]*wx + cam[7]*wy + cam[8]*wz + cam[11];
        const float zc = fmaxf(Zc, 1e-5f);

        const float u  = (Xc * cam[12]) / zc + cam[14];
        const float vv = (Yc * cam[13]) / zc + cam[15];
        const float px = u  * (64.0f/255.0f) - 0.5f;
        const float py = vv * (64.0f/255.0f) - 0.5f;

        const float x0f = floorf(px), y0f = floorf(py);
        const float fx1 = px - x0f,   fy1 = py - y0f;
        const float fx0 = 1.0f - fx1, fy0 = 1.0f - fy1;
        const int ix0 = (int)x0f, iy0 = (int)y0f;
        const int ix1 = ix0 + 1,  iy1 = iy0 + 1;

        const float mx0 = (ix0 >= 0 && ix0 < Wf) ? fx0 : 0.0f;
        const float mx1 = (ix1 >= 0 && ix1 < Wf) ? fx1 : 0.0f;
        const float my0 = (iy0 >= 0 && iy0 < Hf) ? fy0 * 0.25f : 0.0f;
        const float my1 = (iy1 >= 0 && iy1 < Hf) ? fy1 * 0.25f : 0.0f;

        const int bx = min(max(ix0, 0), Wf-2);
        const int by = min(max(iy0, 0), Hf-2);
        const float wqx0 = (ix0 == bx)   ? mx0 : ((ix1 == bx)   ? mx1 : 0.0f);
        const float wqx1 = (ix1 == bx+1) ? mx1 : ((ix0 == bx+1) ? mx0 : 0.0f);
        const float wqy0 = (iy0 == by)   ? my0 : ((iy1 == by)   ? my1 : 0.0f);
        const float wqy1 = (iy1 == by+1) ? my1 : ((iy0 == by+1) ? my0 : 0.0f);

        const float w0 = wqy0*wqx0, w1 = wqy0*wqx1, w2 = wqy1*wqx0, w3 = wqy1*wqx1;
        __half2 h0 = __floats2half2_rn(w0, w0);
        __half2 h1 = __floats2half2_rn(w1, w1);
        __half2 h2 = __floats2half2_rn(w2, w2);
        __half2 h3 = __floats2half2_rn(w3, w3);
        uint4 u4;
        u4.x = *reinterpret_cast<unsigned*>(&h0);
        u4.y = *reinterpret_cast<unsigned*>(&h1);
        u4.z = *reinterpret_cast<unsigned*>(&h2);
        u4.w = *reinterpret_cast<unsigned*>(&h3);
        s_ww[pl][v] = u4;
        reinterpret_cast<int*>(&s_off4[pl])[v] = (by*Wf + bx) * 16;
    }
    __syncthreads();

    // -------- Phase 2: 4-point grouped gather, MLP=8 --------
    {
        const int w    = tid >> 5;
        const int lane = tid & 31;
        const int p    = lane >> 3;          // point within group of 4
        const int q    = lane & 7;           // chpair half-index
        const uint4* qb0 = g_Q + (size_t)(b*Vn)*QV + q;   // +q folded into bases
        const uint4* qb1 = qb0 + QV;
        const uint4* qb2 = qb1 + QV;
        const uint4* qb3 = qb2 + QV;
        const __half2 hz = __floats2half2_rn(0.f, 0.f);

        #pragma unroll
        for (int g = 0; g < 2; g++) {
            const int pl = w*8 + g*4 + p;
            const int4 offs = s_off4[pl];

            // all 8 loads in flight before any consumption
            const uint4 dA0 = __ldg(qb0 + offs.x);
            const uint4 dB0 = __ldg(qb0 + offs.x + 8);
            const uint4 dA1 = __ldg(qb1 + offs.y);
            const uint4 dB1 = __ldg(qb1 + offs.y + 8);
            const uint4 dA2 = __ldg(qb2 + offs.z);
            const uint4 dB2 = __ldg(qb2 + offs.z + 8);
            const uint4 dA3 = __ldg(qb3 + offs.w);
            const uint4 dB3 = __ldg(qb3 + offs.w + 8);

            __half2 aAE = hz, aAO = hz, aBE = hz, aBO = hz;
            const uint4 w0 = s_ww[pl][0];
            FMA4(aAE, w0, dA0); FMA4(aBE, w0, dB0);
            const uint4 w1 = s_ww[pl][1];
            FMA4(aAO, w1, dA1); FMA4(aBO, w1, dB1);
            const uint4 w2 = s_ww[pl][2];
            FMA4(aAE, w2, dA2); FMA4(aBE, w2, dB2);
            const uint4 w3 = s_ww[pl][3];
            FMA4(aAO, w3, dA3); FMA4(aBO, w3, dB3);

            const __half2 sA = __hadd2(aAE, aAO);
            const __half2 sB = __hadd2(aBE, aBO);
            const float2 fA = __half22float2(sA);
            const float2 fB = __half22float2(sB);
            s_acc[pl][2*q     ] = fA.x;      // scalar STS: pad-33 rows are only
            s_acc[pl][2*q + 1 ] = fA.y;      // 4B-aligned, float2 would trap
            s_acc[pl][2*q + 16] = fB.x;
            s_acc[pl][2*q + 17] = fB.y;
        }
    }
    __syncthreads();

    // -------- Phase 3: conflict-free LDS + coalesced STG.32 --------
    {
        const int w  = tid >> 5;
        const int xl = tid & 31;
        #pragma unroll
        for (int k = 0; k < 8; k++) {
            const int c  = (w*8 + k) >> 2;
            const int yl = (w*8 + k) & 3;
            const float val = s_acc[yl*32 + xl][c];
            out[((size_t)(b*Cn + c) << 18) + z0t*4096 + (y0t + yl)*64 + x0t + xl] = val;
        }
    }
}

// ---------------------------------------------------------------------------
extern "C" void kernel_launch(void* const* d_in, const int* in_sizes, int n_in,
                              void* d_out, int out_size) {
    const float* feat = (const float*)d_in[0];
    const float* R    = (const float*)d_in[1];
    const float* T    = (const float*)d_in[2];
    const float* K    = (const float*)d_in[3];
    const float* root = (const float*)d_in[4];
    float* out = (float*)d_out;

    pack_kernel<<<Bz*Vn*64, 512>>>(feat, R, T, K, root);
    sample_kernel<<<Bz*2048, 512>>>(out);
}

// round 16
// speedup vs baseline: 1.0006x; 1.0006x over previous
#include <cuda_runtime.h>
#include <cuda_fp16.h>

#define Bz 2
#define Vn 4
#define Cn 32
#define Hf 64
#define Wf 64
#define Dv 64
#define QV 65536            // uint4 (16B) units per view: 4096 texels x 16 chpairs

// Q layout: [bv][tex][chpair(16)][tap(4)][ch(2)] fp16; texel record = 256B
__device__ uint4 g_Q[Bz*Vn*QV];              // 8 MB
__device__ float g_cam[Bz*Vn][16];

// ---------------------------------------------------------------------------
// Pack: f [bv][c][y][x] fp32 -> g_Q. Block = (bv, y-row), 512 threads.
// ---------------------------------------------------------------------------
__global__ __launch_bounds__(512) void pack_kernel(
        const float* __restrict__ f,
        const float* __restrict__ R, const float* __restrict__ T,
        const float* __restrict__ K, const float* __restrict__ root) {
    __shared__ __half s_f[2][32][66];        // [row][c][x + pad2]
    const int tid = threadIdx.x;
    const int bv  = blockIdx.x >> 6;
    const int y0  = blockIdx.x & 63;

    #pragma unroll
    for (int it = 0; it < 2; it++) {
        const int k   = tid + it*512;
        const int x4  = (k & 15) * 4;
        const int c   = (k >> 4) & 31;
        const int row = k >> 9;
        const int gy  = min(y0 + row, 63);
        const float4 a = __ldg(reinterpret_cast<const float4*>(
            &f[(((bv*Cn + c)*Hf) + gy)*Wf + x4]));
        const __half2 h0 = __floats2half2_rn(a.x, a.y);
        const __half2 h1 = __floats2half2_rn(a.z, a.w);
        *reinterpret_cast<__half2*>(&s_f[row][c][x4    ]) = h0;
        *reinterpret_cast<__half2*>(&s_f[row][c][x4 + 2]) = h1;
    }

    if (blockIdx.x == 0 && tid < Bz*Vn) {
        int i = tid, b = i / Vn;
        const float* Ri = R + i*9; const float* Ti = T + i*3;
        const float* Ki = K + i*9; const float* rb = root + b*3;
        float* o = g_cam[i];
        #pragma unroll
        for (int r = 0; r < 9; r++) o[r] = Ri[r];
        #pragma unroll
        for (int r = 0; r < 3; r++)
            o[9+r] = Ri[r*3+0]*rb[0] + Ri[r*3+1]*rb[1] + Ri[r*3+2]*rb[2] + Ti[r];
        o[12] = Ki[0]; o[13] = Ki[4]; o[14] = Ki[2]; o[15] = Ki[5];
    }
    __syncthreads();

    #pragma unroll
    for (int it = 0; it < 2; it++) {
        const int k = tid + it*512;
        const int q = k & 15;
        const int x = (k >> 4) & 63;
        const int e  = x & ~1;
        const int i0 = x - e;
        const int i1 = min(x + 1, 63) - e;

        uint4 u;
        #pragma unroll
        for (int r = 0; r < 2; r++) {
            const unsigned* rowA = reinterpret_cast<const unsigned*>(&s_f[r][2*q    ][0]);
            const unsigned* rowB = reinterpret_cast<const unsigned*>(&s_f[r][2*q + 1][0]);
            const unsigned A0 = rowA[(e >> 1)    ];
            const unsigned A1 = rowA[(e >> 1) + 1];
            const unsigned B0 = rowB[(e >> 1)    ];
            const unsigned B1 = rowB[(e >> 1) + 1];
            const unsigned vx = __byte_perm(A0, B0, i0 ? 0x7632 : 0x5410);
            const unsigned vy = (i1 == 2) ? __byte_perm(A1, B1, 0x5410)
                                          : __byte_perm(A0, B0, 0x7632);
            if (r == 0) { u.x = vx; u.y = vy; } else { u.z = vx; u.w = vy; }
        }
        g_Q[bv*QV + (y0*64 + x)*16 + q] = u;
    }
}

#define FMA4(acc, ww, d)                                                              \
    acc = __hfma2(*reinterpret_cast<const __half2*>(&(ww).x),                         \
                  *reinterpret_cast<const __half2*>(&(d).x), acc);                    \
    acc = __hfma2(*reinterpret_cast<const __half2*>(&(ww).y),                         \
                  *reinterpret_cast<const __half2*>(&(d).y), acc);                    \
    acc = __hfma2(*reinterpret_cast<const __half2*>(&(ww).z),                         \
                  *reinterpret_cast<const __half2*>(&(d).z), acc);                    \
    acc = __hfma2(*reinterpret_cast<const __half2*>(&(ww).w),                         \
                  *reinterpret_cast<const __half2*>(&(d).w), acc);

// ---------------------------------------------------------------------------
// Main kernel. Tile 32x4x1, 512 threads, 3 blocks/SM.
// Phase 1: camera constants read as 4x LDS.128 (float4) per thread.
// Phase 2: R13-exact 4-point grouped gather (MLP=4, 4+4 split).
// ---------------------------------------------------------------------------
__global__ __launch_bounds__(512, 3) void sample_kernel(float* __restrict__ out) {
    __shared__ float4 s_cam4[16];            // 4 views x 4 float4
    __shared__ uint4  s_ww[128][Vn];
    __shared__ int4   s_off4[128];
    __shared__ float  s_acc[128][Cn + 1];

    const int tid = threadIdx.x;
    const int bid = blockIdx.x;
    const int b   = bid >> 11;
    const int t   = bid & 2047;
    const int x0t = (t & 1) * 32;
    const int y0t = ((t >> 1) & 15) * 4;
    const int z0t = t >> 5;

    if (tid < 16)
        s_cam4[tid] = reinterpret_cast<const float4*>(g_cam)[b*16 + tid];
    __syncthreads();

    // -------- Phase 1: projection + weight remap --------
    {
        const int pl = tid >> 2;
        const int v  = tid & 3;
        const int xi = x0t + (pl & 31);
        const int yi = y0t + (pl >> 5);
        const int zi = z0t;

        const float wx = (xi * (1.0f/63.0f) - 0.5f) * 0.2f;
        const float wy = (yi * (1.0f/63.0f) - 0.5f) * 0.2f;
        const float wz = (zi * (1.0f/63.0f) - 0.5f) * 0.2f;

        // cam layout: [R0..R8, T0,T1,T2, fx,fy,cx,cy] as 4 float4
        const float4 cA = s_cam4[v*4 + 0];   // R0 R1 R2 R3
        const float4 cB = s_cam4[v*4 + 1];   // R4 R5 R6 R7
        const float4 cC = s_cam4[v*4 + 2];   // R8 T0 T1 T2
        const float4 cD = s_cam4[v*4 + 3];   // fx fy cx cy

        const float Xc = cA.x*wx + cA.y*wy + cA.z*wz + cC.y;
        const float Yc = cA.w*wx + cB.x*wy + cB.y*wz + cC.z;
        const float Zc = cB.z*wx + cB.w*wy + cC.x*wz + cC.w;
        const float zc = fmaxf(Zc, 1e-5f);

        const float u  = (Xc * cD.x) / zc + cD.z;
        const float vv = (Yc * cD.y) / zc + cD.w;
        const float px = u  * (64.0f/255.0f) - 0.5f;
        const float py = vv * (64.0f/255.0f) - 0.5f;

        const float x0f = floorf(px), y0f = floorf(py);
        const float fx1 = px - x0f,   fy1 = py - y0f;
        const float fx0 = 1.0f - fx1, fy0 = 1.0f - fy1;
        const int ix0 = (int)x0f, iy0 = (int)y0f;
        const int ix1 = ix0 + 1,  iy1 = iy0 + 1;

        const float mx0 = (ix0 >= 0 && ix0 < Wf) ? fx0 : 0.0f;
        const float mx1 = (ix1 >= 0 && ix1 < Wf) ? fx1 : 0.0f;
        const float my0 = (iy0 >= 0 && iy0 < Hf) ? fy0 * 0.25f : 0.0f;
        const float my1 = (iy1 >= 0 && iy1 < Hf) ? fy1 * 0.25f : 0.0f;

        const int bx = min(max(ix0, 0), Wf-2);
        const int by = min(max(iy0, 0), Hf-2);
        const float wqx0 = (ix0 == bx)   ? mx0 : ((ix1 == bx)   ? mx1 : 0.0f);
        const float wqx1 = (ix1 == bx+1) ? mx1 : ((ix0 == bx+1) ? mx0 : 0.0f);
        const float wqy0 = (iy0 == by)   ? my0 : ((iy1 == by)   ? my1 : 0.0f);
        const float wqy1 = (iy1 == by+1) ? my1 : ((iy0 == by+1) ? my0 : 0.0f);

        const float w0 = wqy0*wqx0, w1 = wqy0*wqx1, w2 = wqy1*wqx0, w3 = wqy1*wqx1;
        __half2 h0 = __floats2half2_rn(w0, w0);
        __half2 h1 = __floats2half2_rn(w1, w1);
        __half2 h2 = __floats2half2_rn(w2, w2);
        __half2 h3 = __floats2half2_rn(w3, w3);
        uint4 u4;
        u4.x = *reinterpret_cast<unsigned*>(&h0);
        u4.y = *reinterpret_cast<unsigned*>(&h1);
        u4.z = *reinterpret_cast<unsigned*>(&h2);
        u4.w = *reinterpret_cast<unsigned*>(&h3);
        s_ww[pl][v] = u4;
        reinterpret_cast<int*>(&s_off4[pl])[v] = (by*Wf + bx) * 16;   // uint4 units
    }
    __syncthreads();

    // -------- Phase 2: 4-point grouped gather (R13-exact), MLP=4 --------
    {
        const int w    = tid >> 5;
        const int lane = tid & 31;
        const int p    = lane >> 3;          // point within group of 4
        const int q    = lane & 7;           // chpair half-index
        const uint4* qb = g_Q + (size_t)(b*Vn)*QV;
        const __half2 hz = __floats2half2_rn(0.f, 0.f);

        #pragma unroll
        for (int g = 0; g < 2; g++) {
            const int pl = w*8 + g*4 + p;
            const int4 offs = s_off4[pl];
            __half2 aAE = hz, aAO = hz, aBE = hz, aBO = hz;

            {   // views 0 & 1
                const uint4 dA0 = __ldg(qb + 0*QV + offs.x + q);
                const uint4 dB0 = __ldg(qb + 0*QV + offs.x + q + 8);
                const uint4 dA1 = __ldg(qb + 1*QV + offs.y + q);
                const uint4 dB1 = __ldg(qb + 1*QV + offs.y + q + 8);
                const uint4 w0 = s_ww[pl][0];
                FMA4(aAE, w0, dA0); FMA4(aBE, w0, dB0);
                const uint4 w1 = s_ww[pl][1];
                FMA4(aAO, w1, dA1); FMA4(aBO, w1, dB1);
            }
            {   // views 2 & 3
                const uint4 dA2 = __ldg(qb + 2*QV + offs.z + q);
                const uint4 dB2 = __ldg(qb + 2*QV + offs.z + q + 8);
                const uint4 dA3 = __ldg(qb + 3*QV + offs.w + q);
                const uint4 dB3 = __ldg(qb + 3*QV + offs.w + q + 8);
                const uint4 w2 = s_ww[pl][2];
                FMA4(aAE, w2, dA2); FMA4(aBE, w2, dB2);
                const uint4 w3 = s_ww[pl][3];
                FMA4(aAO, w3, dA3); FMA4(aBO, w3, dB3);
            }

            const __half2 sA = __hadd2(aAE, aAO);
            const __half2 sB = __hadd2(aBE, aBO);
            const float2 fA = __half22float2(sA);
            const float2 fB = __half22float2(sB);
            s_acc[pl][2*q     ] = fA.x;
            s_acc[pl][2*q + 1 ] = fA.y;
            s_acc[pl][2*q + 16] = fB.x;
            s_acc[pl][2*q + 17] = fB.y;
        }
    }
    __syncthreads();

    // -------- Phase 3: conflict-free LDS + coalesced STG.32 --------
    {
        const int w  = tid >> 5;
        const int xl = tid & 31;
        #pragma unroll
        for (int k = 0; k < 8; k++) {
            const int c  = (w*8 + k) >> 2;
            const int yl = (w*8 + k) & 3;
            const float val = s_acc[yl*32 + xl][c];
            out[((size_t)(b*Cn + c) << 18) + z0t*4096 + (y0t + yl)*64 + x0t + xl] = val;
        }
    }
}

// ---------------------------------------------------------------------------
extern "C" void kernel_launch(void* const* d_in, const int* in_sizes, int n_in,
                              void* d_out, int out_size) {
    const float* feat = (const float*)d_in[0];
    const float* R    = (const float*)d_in[1];
    const float* T    = (const float*)d_in[2];
    const float* K    = (const float*)d_in[3];
    const float* root = (const float*)d_in[4];
    float* out = (float*)d_out;

    pack_kernel<<<Bz*Vn*64, 512>>>(feat, R, T, K, root);
    sample_kernel<<<Bz*2048, 512>>>(out);
}